// round 16
// baseline (speedup 1.0000x reference)
#include <cuda_runtime.h>
#include <cuda_fp16.h>
#include <cuda_fp8.h>
#include <math.h>
#include <float.h>

#define NV 100000
#define EV 1600000
#define ET 1700000   // EV + NV self loops
#define FULLMASK 0xffffffffu

// ---------------- scratch (static device globals; no allocation) ----------------
__device__ int    g_deg[NV];
__device__ float  g_dinv[NV];
__device__ int    g_rowptr[NV + 1];
__device__ int    g_cursor[NV];
__device__ int    g_bsum[128];
__device__ int2   g_edge[ET];          // (src, weight as packed half2(w,w))
__device__ __align__(16) unsigned int g_h[11][NV * 32];  // h_0..h_10, [N,128] fp8 e4m3
__device__ __align__(16) __half2 g_h1h[NV * 32];  // [N,64] half (GAT1 features)
__device__ float  g_als1[NV * 8];
__device__ float  g_ald1[NV * 8];
__device__ __align__(16) __half2 g_act1h[NV * 32];  // [N,64] after ELU (half)
__device__ __align__(16) __half g_h2h[NV * 64];  // [N,64] half, ch 40..63 stay zero
__device__ float  g_als2[NV];
__device__ float  g_ald2[NV];

// ---------------- fp8 / packed helpers ----------------
__device__ __forceinline__ unsigned int pack_fp8x4(float a, float b, float c, float d) {
    __nv_fp8x2_storage_t lo = __nv_cvt_float2_to_fp8x2(make_float2(a, b), __NV_SATFINITE, __NV_E4M3);
    __nv_fp8x2_storage_t hi = __nv_cvt_float2_to_fp8x2(make_float2(c, d), __NV_SATFINITE, __NV_E4M3);
    return (unsigned int)lo | ((unsigned int)hi << 16);
}
__device__ __forceinline__ void unpack_fp8x4(unsigned int u, float2& lo, float2& hi) {
    __half2_raw rl = __nv_cvt_fp8x2_to_halfraw2((__nv_fp8x2_storage_t)(u & 0xffffu), __NV_E4M3);
    __half2_raw rh = __nv_cvt_fp8x2_to_halfraw2((__nv_fp8x2_storage_t)(u >> 16), __NV_E4M3);
    lo = __half22float2(*reinterpret_cast<__half2*>(&rl));
    hi = __half22float2(*reinterpret_cast<__half2*>(&rh));
}
__device__ __forceinline__ __half2 fp8lo_h2(unsigned int v) {
    __half2_raw r = __nv_cvt_fp8x2_to_halfraw2((__nv_fp8x2_storage_t)(v & 0xffffu), __NV_E4M3);
    return *reinterpret_cast<__half2*>(&r);
}
__device__ __forceinline__ __half2 fp8hi_h2(unsigned int v) {
    __half2_raw r = __nv_cvt_fp8x2_to_halfraw2((__nv_fp8x2_storage_t)(v >> 16), __NV_E4M3);
    return *reinterpret_cast<__half2*>(&r);
}
__device__ __forceinline__ float2 h2f2(unsigned int v) {
    return __half22float2(*reinterpret_cast<__half2*>(&v));
}
__device__ __forceinline__ int pack_w_h2(float w) {
    __half2 h = __float2half2_rn(w);
    return *reinterpret_cast<int*>(&h);
}
__device__ __forceinline__ void fma_f32x2(unsigned long long& acc,
                                          unsigned long long a, unsigned long long b) {
    asm("fma.rn.f32x2 %0, %1, %2, %0;" : "+l"(acc) : "l"(a), "l"(b));
}

// ---------------- CSR construction ----------------
__global__ void k_count(const int* __restrict__ ei) {
    int stride = gridDim.x * blockDim.x;
    for (int i = blockIdx.x * blockDim.x + threadIdx.x; i < EV; i += stride)
        atomicAdd(&g_deg[ei[EV + i]], 1);
}

// scan over (deg+1); also computes dinv. g_deg itself is never read afterwards.
__global__ __launch_bounds__(1024) void k_scan1() {
    __shared__ int sh[1024];
    int i = blockIdx.x * 1024 + threadIdx.x;
    int v = 0;
    if (i < NV) {
        v = g_deg[i] + 1;   // + self loop
        g_dinv[i] = rsqrtf((float)v);
    }
    sh[threadIdx.x] = v;
    __syncthreads();
    for (int off = 1; off < 1024; off <<= 1) {
        int tv = (threadIdx.x >= off) ? sh[threadIdx.x - off] : 0;
        __syncthreads();
        sh[threadIdx.x] += tv;
        __syncthreads();
    }
    if (i < NV) g_rowptr[i] = sh[threadIdx.x] - v;
    if (threadIdx.x == 1023) g_bsum[blockIdx.x] = sh[1023];
}

__global__ void k_scan2(int nb) {
    if (threadIdx.x == 0) {
        int s = 0;
        for (int i = 0; i < nb; i++) { int v = g_bsum[i]; g_bsum[i] = s; s += v; }
    }
}

__global__ void k_scan3() {
    int i = blockIdx.x * blockDim.x + threadIdx.x;
    if (i < NV) {
        int r = g_rowptr[i] + g_bsum[i >> 10];
        g_rowptr[i] = r;
        g_cursor[i] = r;
    }
    if (i == 0) g_rowptr[NV] = ET;
}

__global__ void k_fill_edges(const int* __restrict__ ei) {
    int stride = gridDim.x * blockDim.x;
    for (int i = blockIdx.x * blockDim.x + threadIdx.x; i < EV; i += stride) {
        int s = ei[i], d = ei[EV + i];
        int pos = atomicAdd(&g_cursor[d], 1);
        g_edge[pos] = make_int2(s, pack_w_h2(g_dinv[s] * g_dinv[d]));
    }
}

__global__ void k_fill_self() {
    int i = blockIdx.x * blockDim.x + threadIdx.x;
    if (i < NV) {
        int pos = atomicAdd(&g_cursor[i], 1);
        float di = g_dinv[i];
        g_edge[pos] = make_int2(i, pack_w_h2(di * di));
    }
}

// ---------------- diffusion ----------------
__global__ void k_init_h0(const float* __restrict__ x) {
    int i = blockIdx.x * blockDim.x + threadIdx.x;
    if (i >= NV * 32) return;
    float4 xv = reinterpret_cast<const float4*>(x)[i];
    g_h[0][i] = pack_fp8x4(xv.x, xv.y, xv.z, xv.w);
}

// 4 edges per LDG.128 -- plain dynamic loop (compiler pipelines), unroll 8
__global__ __launch_bounds__(256) void k_hop(const unsigned int* __restrict__ hin,
                                             unsigned int* __restrict__ hout) {
    int w = (blockIdx.x * blockDim.x + threadIdx.x) >> 5;
    int lane = threadIdx.x & 31;
    if (w >= NV) return;
    int g = lane >> 3;
    int p = lane & 7;

    int beg = g_rowptr[w], end = g_rowptr[w + 1];
    __half2 acc[8];
    #pragma unroll
    for (int i = 0; i < 8; i++) acc[i] = __float2half2_rn(0.f);

    for (int base = beg; base < end; base += 32) {
        int cnt = min(32, end - base);
        int2 e = (lane < cnt) ? g_edge[base + lane] : make_int2(0, 0);  // pad: s=0, w=0
        int steps = (cnt + 3) >> 2;
        #pragma unroll 8
        for (int st = 0; st < steps; st++) {
            int jj = st * 4 + g;
            int s  = __shfl_sync(FULLMASK, e.x, jj);
            int wb = __shfl_sync(FULLMASK, e.y, jj);
            __half2 hw = *reinterpret_cast<__half2*>(&wb);   // pre-splatted half2(w,w)
            uint4 u = __ldg(reinterpret_cast<const uint4*>(hin + s * 32) + p);
            acc[0] = __hfma2(hw, fp8lo_h2(u.x), acc[0]);
            acc[1] = __hfma2(hw, fp8hi_h2(u.x), acc[1]);
            acc[2] = __hfma2(hw, fp8lo_h2(u.y), acc[2]);
            acc[3] = __hfma2(hw, fp8hi_h2(u.y), acc[3]);
            acc[4] = __hfma2(hw, fp8lo_h2(u.z), acc[4]);
            acc[5] = __hfma2(hw, fp8hi_h2(u.z), acc[5]);
            acc[6] = __hfma2(hw, fp8lo_h2(u.w), acc[6]);
            acc[7] = __hfma2(hw, fp8hi_h2(u.w), acc[7]);
        }
    }
    #pragma unroll
    for (int i = 0; i < 8; i++) {
        unsigned int v = *reinterpret_cast<unsigned int*>(&acc[i]);
        unsigned int o = __shfl_xor_sync(FULLMASK, v, 8);
        __half2 tt = __hadd2(acc[i], *reinterpret_cast<__half2*>(&o));
        unsigned int v2 = *reinterpret_cast<unsigned int*>(&tt);
        unsigned int o2 = __shfl_xor_sync(FULLMASK, v2, 16);
        acc[i] = __hadd2(tt, *reinterpret_cast<__half2*>(&o2));
    }
    if (g == 0) {
        unsigned int r[4];
        #pragma unroll
        for (int i = 0; i < 4; i++) {
            __half2_raw a = *reinterpret_cast<__half2_raw*>(&acc[2 * i]);
            __half2_raw b = *reinterpret_cast<__half2_raw*>(&acc[2 * i + 1]);
            unsigned int lo = __nv_cvt_halfraw2_to_fp8x2(a, __NV_SATFINITE, __NV_E4M3);
            unsigned int hi = __nv_cvt_halfraw2_to_fp8x2(b, __NV_SATFINITE, __NV_E4M3);
            r[i] = lo | (hi << 16);
        }
        reinterpret_cast<uint4*>(hout + w * 32)[p] = make_uint4(r[0], r[1], r[2], r[3]);
    }
}

// -------- GEMM1 [N,128]@[128,64] + Taylor combine + attention logits --------
__global__ __launch_bounds__(256) void k_gemm1(const float* __restrict__ t,
                                               const float* __restrict__ W1,
                                               const float* __restrict__ as1,
                                               const float* __restrict__ ad1) {
    __shared__ __align__(16) float sW[64 * 64];
    __shared__ float sX[32][132];
    int tid = threadIdx.x;
    int nb = blockIdx.x * 32;

    for (int i = tid; i < 1024; i += 256) {
        int r = i >> 5, q = i & 31;
        int n = nb + r;
        float4 a = make_float4(0, 0, 0, 0);
        if (n < NV) {
            float4 tv = reinterpret_cast<const float4*>(t)[q];
            float4 cf;
            cf.x = __expf(-tv.x); cf.y = __expf(-tv.y);
            cf.z = __expf(-tv.z); cf.w = __expf(-tv.w);
            #pragma unroll
            for (int k = 0; k <= 10; k++) {
                if (k > 0) {
                    float inv = 1.f / (float)k;
                    cf.x *= tv.x * inv; cf.y *= tv.y * inv;
                    cf.z *= tv.z * inv; cf.w *= tv.w * inv;
                }
                unsigned int u = __ldg(&g_h[k][n * 32 + q]);
                float2 lo, hi;
                unpack_fp8x4(u, lo, hi);
                a.x = fmaf(cf.x, lo.x, a.x); a.y = fmaf(cf.y, lo.y, a.y);
                a.z = fmaf(cf.z, hi.x, a.z); a.w = fmaf(cf.w, hi.y, a.w);
            }
        }
        *reinterpret_cast<float4*>(&sX[r][q * 4]) = a;
    }

    int node = tid >> 3, cs = tid & 7;
    unsigned long long acc2[4] = {0, 0, 0, 0};
    for (int ph = 0; ph < 2; ph++) {
        __syncthreads();
        const float4* W4 = reinterpret_cast<const float4*>(W1) + ph * 1024;
        for (int i = tid; i < 1024; i += 256) reinterpret_cast<float4*>(sW)[i] = W4[i];
        __syncthreads();
        const ulonglong2* sW2 = reinterpret_cast<const ulonglong2*>(sW);
        #pragma unroll 8
        for (int kk = 0; kk < 64; kk++) {
            float xv = sX[node][ph * 64 + kk];
            unsigned long long xv2;
            asm("mov.b64 %0, {%1, %1};" : "=l"(xv2) : "r"(__float_as_uint(xv)));
            ulonglong2 wa = sW2[kk * 16 + cs * 2];
            ulonglong2 wb = sW2[kk * 16 + cs * 2 + 1];
            fma_f32x2(acc2[0], xv2, wa.x);
            fma_f32x2(acc2[1], xv2, wa.y);
            fma_f32x2(acc2[2], xv2, wb.x);
            fma_f32x2(acc2[3], xv2, wb.y);
        }
    }
    float av[8];
    #pragma unroll
    for (int i = 0; i < 4; i++) {
        unsigned int lo, hi;
        asm("mov.b64 {%0, %1}, %2;" : "=r"(lo), "=r"(hi) : "l"(acc2[i]));
        av[2 * i]     = __uint_as_float(lo);
        av[2 * i + 1] = __uint_as_float(hi);
    }
    int n = nb + node;
    if (n < NV) {
        __half2* pp = &g_h1h[n * 32 + cs * 4];
        pp[0] = __floats2half2_rn(av[0], av[1]);
        pp[1] = __floats2half2_rn(av[2], av[3]);
        pp[2] = __floats2half2_rn(av[4], av[5]);
        pp[3] = __floats2half2_rn(av[6], av[7]);
        const float* s8 = as1 + cs * 8;
        const float* d8 = ad1 + cs * 8;
        float ls = 0.f, ld_ = 0.f;
        #pragma unroll
        for (int i = 0; i < 8; i++) { ls += av[i] * s8[i]; ld_ += av[i] * d8[i]; }
        g_als1[n * 8 + cs] = ls;
        g_ald1[n * 8 + cs] = ld_;
    }
}

// ---- GAT1: 4 edges/LDG.128 (lane p = head p), plain dynamic loop; no-shift softmax ----
__global__ __launch_bounds__(256) void k_gat1(const float* __restrict__ b1) {
    int w = (blockIdx.x * blockDim.x + threadIdx.x) >> 5;
    int lane = threadIdx.x & 31;
    if (w >= NV) return;
    int g = lane >> 3;
    int p = lane & 7;
    float adn = g_ald1[w * 8 + p];
    int beg = g_rowptr[w], end = g_rowptr[w + 1];

    float den = 0.f;
    float acc[8] = {0, 0, 0, 0, 0, 0, 0, 0};

    for (int base = beg; base < end; base += 32) {
        int cnt = min(32, end - base);
        int sv = (lane < cnt) ? g_edge[base + lane].x : 0;
        int steps = (cnt + 3) >> 2;
        #pragma unroll 2
        for (int st = 0; st < steps; st++) {
            int jj = st * 4 + g;
            int s = __shfl_sync(FULLMASK, sv, jj);
            uint4 u = __ldg(reinterpret_cast<const uint4*>(g_h1h + (size_t)s * 32) + p);
            float al = __ldg(&g_als1[s * 8 + p]);
            float e = al + adn;
            e = (e > 0.f) ? e : 0.2f * e;
            float ex = (jj < cnt) ? __expf(e) : 0.f;
            den += ex;
            float2 f0 = h2f2(u.x);
            float2 f1 = h2f2(u.y);
            float2 f2 = h2f2(u.z);
            float2 f3 = h2f2(u.w);
            acc[0] = fmaf(ex, f0.x, acc[0]); acc[1] = fmaf(ex, f0.y, acc[1]);
            acc[2] = fmaf(ex, f1.x, acc[2]); acc[3] = fmaf(ex, f1.y, acc[3]);
            acc[4] = fmaf(ex, f2.x, acc[4]); acc[5] = fmaf(ex, f2.y, acc[5]);
            acc[6] = fmaf(ex, f3.x, acc[6]); acc[7] = fmaf(ex, f3.y, acc[7]);
        }
    }
    den += __shfl_xor_sync(FULLMASK, den, 8);
    den += __shfl_xor_sync(FULLMASK, den, 16);
    #pragma unroll
    for (int i = 0; i < 8; i++) {
        acc[i] += __shfl_xor_sync(FULLMASK, acc[i], 8);
        acc[i] += __shfl_xor_sync(FULLMASK, acc[i], 16);
    }
    if (g == 0) {
        float inv = 1.f / fmaxf(den, 1e-16f);
        float v[8];
        #pragma unroll
        for (int i = 0; i < 8; i++) {
            float x = acc[i] * inv + b1[p * 8 + i];
            v[i] = (x > 0.f) ? x : expm1f(x);
        }
        unsigned int r[4];
        #pragma unroll
        for (int i = 0; i < 4; i++) {
            __half2 hh = __floats2half2_rn(v[2 * i], v[2 * i + 1]);
            r[i] = *reinterpret_cast<unsigned int*>(&hh);
        }
        reinterpret_cast<uint4*>(g_act1h + (size_t)w * 32)[p] = make_uint4(r[0], r[1], r[2], r[3]);
    }
}

// ---------------- GEMM2 [N,64]@[64,40] + logits (h2 padded to 64 ch) ----------------
__global__ __launch_bounds__(256) void k_gemm2(const float* __restrict__ W2,
                                               const float* __restrict__ as2,
                                               const float* __restrict__ ad2) {
    __shared__ float sW[64 * 40];
    __shared__ float sX[32][68];
    int tid = threadIdx.x;
    int nb = blockIdx.x * 32;
    for (int i = tid; i < 2560; i += 256) sW[i] = W2[i];
    for (int i = tid; i < 512; i += 256) {
        int r = i >> 4, q = i & 15;
        int n = nb + r;
        float4 v = make_float4(0, 0, 0, 0);
        if (n < NV) {
            __half2 h0 = g_act1h[n * 32 + q * 2];
            __half2 h1 = g_act1h[n * 32 + q * 2 + 1];
            float2 f0 = __half22float2(h0);
            float2 f1 = __half22float2(h1);
            v = make_float4(f0.x, f0.y, f1.x, f1.y);
        }
        *reinterpret_cast<float4*>(&sX[r][q * 4]) = v;
    }
    __syncthreads();
    int node = tid >> 3, cs = tid & 7;
    float a[5] = {0, 0, 0, 0, 0};
    #pragma unroll 4
    for (int kk = 0; kk < 64; kk++) {
        float xv = sX[node][kk];
        #pragma unroll
        for (int i = 0; i < 5; i++) a[i] = fmaf(xv, sW[kk * 40 + cs * 5 + i], a[i]);
    }
    int n = nb + node;
    float ps = 0.f, pd = 0.f;
    #pragma unroll
    for (int i = 0; i < 5; i++) { ps += a[i] * as2[cs * 5 + i]; pd += a[i] * ad2[cs * 5 + i]; }
    ps += __shfl_xor_sync(FULLMASK, ps, 1);
    ps += __shfl_xor_sync(FULLMASK, ps, 2);
    ps += __shfl_xor_sync(FULLMASK, ps, 4);
    pd += __shfl_xor_sync(FULLMASK, pd, 1);
    pd += __shfl_xor_sync(FULLMASK, pd, 2);
    pd += __shfl_xor_sync(FULLMASK, pd, 4);
    if (n < NV) {
        #pragma unroll
        for (int i = 0; i < 5; i++) g_h2h[n * 64 + cs * 5 + i] = __float2half(a[i]);
        if (cs == 0) { g_als2[n] = ps; g_ald2[n] = pd; }
    }
}

// ---- GAT2: 4 edges/LDG.128 (64-ch padded rows), plain loop + log_softmax -> out ----
__global__ __launch_bounds__(256) void k_gat2(const float* __restrict__ b2,
                                              float* __restrict__ out) {
    int w = (blockIdx.x * blockDim.x + threadIdx.x) >> 5;
    int lane = threadIdx.x & 31;
    if (w >= NV) return;
    int g = lane >> 3;
    int p = lane & 7;
    float adn = g_ald2[w];
    int beg = g_rowptr[w], end = g_rowptr[w + 1];

    float den = 0.f;
    float acc[8] = {0, 0, 0, 0, 0, 0, 0, 0};

    for (int base = beg; base < end; base += 32) {
        int cnt = min(32, end - base);
        int sv = (lane < cnt) ? g_edge[base + lane].x : 0;
        int steps = (cnt + 3) >> 2;
        #pragma unroll 2
        for (int st = 0; st < steps; st++) {
            int jj = st * 4 + g;
            int s = __shfl_sync(FULLMASK, sv, jj);
            uint4 u = __ldg(reinterpret_cast<const uint4*>(g_h2h + (size_t)s * 64) + p);
            float al = __ldg(&g_als2[s]);
            float e = al + adn;
            e = (e > 0.f) ? e : 0.2f * e;
            float ex = (jj < cnt) ? __expf(e) : 0.f;
            den += ex;
            float2 f0 = h2f2(u.x);
            float2 f1 = h2f2(u.y);
            float2 f2 = h2f2(u.z);
            float2 f3 = h2f2(u.w);
            acc[0] = fmaf(ex, f0.x, acc[0]); acc[1] = fmaf(ex, f0.y, acc[1]);
            acc[2] = fmaf(ex, f1.x, acc[2]); acc[3] = fmaf(ex, f1.y, acc[3]);
            acc[4] = fmaf(ex, f2.x, acc[4]); acc[5] = fmaf(ex, f2.y, acc[5]);
            acc[6] = fmaf(ex, f3.x, acc[6]); acc[7] = fmaf(ex, f3.y, acc[7]);
        }
    }
    den += __shfl_xor_sync(FULLMASK, den, 8);
    den += __shfl_xor_sync(FULLMASK, den, 16);
    #pragma unroll
    for (int i = 0; i < 8; i++) {
        acc[i] += __shfl_xor_sync(FULLMASK, acc[i], 8);
        acc[i] += __shfl_xor_sync(FULLMASK, acc[i], 16);
    }

    float inv = 1.f / fmaxf(den, 1e-16f);
    float v[8];
    float m = -FLT_MAX;
    #pragma unroll
    for (int i = 0; i < 8; i++) {
        float x = (p < 5) ? (acc[i] * inv + __ldg(&b2[min(p * 8 + i, 39)])) : -FLT_MAX;
        v[i] = x;
        m = fmaxf(m, x);
    }
    m = fmaxf(m, __shfl_xor_sync(FULLMASK, m, 1));
    m = fmaxf(m, __shfl_xor_sync(FULLMASK, m, 2));
    m = fmaxf(m, __shfl_xor_sync(FULLMASK, m, 4));
    float se = 0.f;
    #pragma unroll
    for (int i = 0; i < 8; i++) se += (p < 5) ? __expf(v[i] - m) : 0.f;
    se += __shfl_xor_sync(FULLMASK, se, 1);
    se += __shfl_xor_sync(FULLMASK, se, 2);
    se += __shfl_xor_sync(FULLMASK, se, 4);
    float lse = logf(se) + m;
    if (g == 0 && p < 5) {
        float4* dst = reinterpret_cast<float4*>(out + (size_t)w * 40 + p * 8);
        dst[0] = make_float4(v[0] - lse, v[1] - lse, v[2] - lse, v[3] - lse);
        dst[1] = make_float4(v[4] - lse, v[5] - lse, v[6] - lse, v[7] - lse);
    }
}

// ---------------- launch ----------------
extern "C" void kernel_launch(void* const* d_in, const int* in_sizes, int n_in,
                              void* d_out, int out_size) {
    const float* x   = (const float*)d_in[0];
    const int*   ei  = (const int*)d_in[1];
    const float* t   = (const float*)d_in[2];
    const float* W1  = (const float*)d_in[3];
    const float* as1 = (const float*)d_in[4];
    const float* ad1 = (const float*)d_in[5];
    const float* b1  = (const float*)d_in[6];
    const float* W2  = (const float*)d_in[7];
    const float* as2 = (const float*)d_in[8];
    const float* ad2 = (const float*)d_in[9];
    const float* b2  = (const float*)d_in[10];
    float* out = (float*)d_out;

    const int NB  = (NV + 255) / 256;
    const int NWB = (NV * 32 + 255) / 256;
    const int SB  = (NV + 1023) / 1024;

    // CSR build (zero_deg via memsetAsync; finish_deg folded into scan1)
    int* degAddr;
    cudaGetSymbolAddress((void**)&degAddr, g_deg);
    cudaMemsetAsync(degAddr, 0, NV * sizeof(int));
    k_count<<<2048, 256>>>(ei);
    k_scan1<<<SB, 1024>>>();
    k_scan2<<<1, 32>>>(SB);
    k_scan3<<<NB, 256>>>();
    k_fill_edges<<<2048, 256>>>(ei);
    k_fill_self<<<NB, 256>>>();

    // diffusion hops: h_k = A_hat h_{k-1}, features in fp8 e4m3
    k_init_h0<<<NWB, 256>>>(x);
    unsigned int* hbase;
    cudaGetSymbolAddress((void**)&hbase, g_h);
    for (int k = 1; k <= 10; k++)
        k_hop<<<NWB, 256>>>(hbase + (size_t)(k - 1) * NV * 32,
                            hbase + (size_t)k * NV * 32);

    // GAT layer 1 (Taylor combine fused into staging)
    k_gemm1<<<(NV + 31) / 32, 256>>>(t, W1, as1, ad1);
    k_gat1<<<NWB, 256>>>(b1);

    // GAT layer 2 + log_softmax
    k_gemm2<<<(NV + 31) / 32, 256>>>(W2, as2, ad2);
    k_gat2<<<NWB, 256>>>(b2, out);
}

// round 17
// speedup vs baseline: 1.0955x; 1.0955x over previous
#include <cuda_runtime.h>
#include <cuda_fp16.h>
#include <cuda_fp8.h>
#include <math.h>
#include <float.h>

#define NV 100000
#define EV 1600000
#define ET 1700000   // EV + NV self loops
#define FULLMASK 0xffffffffu

// ---------------- scratch (static device globals; no allocation) ----------------
__device__ int    g_deg[NV];
__device__ float  g_dinv[NV];
__device__ int    g_rowptr[NV + 1];
__device__ int    g_cursor[NV];
__device__ int    g_bsum[128];
__device__ int2   g_edge[ET];          // (src, weight as packed half2(w,w))
__device__ __align__(16) unsigned int g_h[11][NV * 32];  // h_0..h_10, [N,128] fp8 e4m3
__device__ __align__(16) __half2 g_h1h[NV * 32];  // [N,64] half (GAT1 features)
__device__ float  g_als1[NV * 8];
__device__ float  g_ald1[NV * 8];
__device__ __align__(16) __half2 g_act1h[NV * 32];  // [N,64] after ELU (half)
__device__ __align__(16) __half g_h2h[NV * 64];  // [N,64] half, ch 40..63 stay zero
__device__ float  g_als2[NV];
__device__ float  g_ald2[NV];

// ---------------- fp8 / packed helpers ----------------
__device__ __forceinline__ unsigned int pack_fp8x4(float a, float b, float c, float d) {
    __nv_fp8x2_storage_t lo = __nv_cvt_float2_to_fp8x2(make_float2(a, b), __NV_SATFINITE, __NV_E4M3);
    __nv_fp8x2_storage_t hi = __nv_cvt_float2_to_fp8x2(make_float2(c, d), __NV_SATFINITE, __NV_E4M3);
    return (unsigned int)lo | ((unsigned int)hi << 16);
}
__device__ __forceinline__ void unpack_fp8x4(unsigned int u, float2& lo, float2& hi) {
    __half2_raw rl = __nv_cvt_fp8x2_to_halfraw2((__nv_fp8x2_storage_t)(u & 0xffffu), __NV_E4M3);
    __half2_raw rh = __nv_cvt_fp8x2_to_halfraw2((__nv_fp8x2_storage_t)(u >> 16), __NV_E4M3);
    lo = __half22float2(*reinterpret_cast<__half2*>(&rl));
    hi = __half22float2(*reinterpret_cast<__half2*>(&rh));
}
__device__ __forceinline__ __half2 fp8lo_h2(unsigned int v) {
    __half2_raw r = __nv_cvt_fp8x2_to_halfraw2((__nv_fp8x2_storage_t)(v & 0xffffu), __NV_E4M3);
    return *reinterpret_cast<__half2*>(&r);
}
__device__ __forceinline__ __half2 fp8hi_h2(unsigned int v) {
    __half2_raw r = __nv_cvt_fp8x2_to_halfraw2((__nv_fp8x2_storage_t)(v >> 16), __NV_E4M3);
    return *reinterpret_cast<__half2*>(&r);
}
__device__ __forceinline__ float2 h2f2(unsigned int v) {
    return __half22float2(*reinterpret_cast<__half2*>(&v));
}
__device__ __forceinline__ int pack_w_h2(float w) {
    __half2 h = __float2half2_rn(w);
    return *reinterpret_cast<int*>(&h);
}
__device__ __forceinline__ void fma_f32x2(unsigned long long& acc,
                                          unsigned long long a, unsigned long long b) {
    asm("fma.rn.f32x2 %0, %1, %2, %0;" : "+l"(acc) : "l"(a), "l"(b));
}

// ---------------- CSR construction ----------------
__global__ void k_count(const int* __restrict__ ei) {
    int stride = gridDim.x * blockDim.x;
    for (int i = blockIdx.x * blockDim.x + threadIdx.x; i < EV; i += stride)
        atomicAdd(&g_deg[ei[EV + i]], 1);
}

// scan over (deg+1); also computes dinv. g_deg itself is never read afterwards.
__global__ __launch_bounds__(1024) void k_scan1() {
    __shared__ int sh[1024];
    int i = blockIdx.x * 1024 + threadIdx.x;
    int v = 0;
    if (i < NV) {
        v = g_deg[i] + 1;   // + self loop
        g_dinv[i] = rsqrtf((float)v);
    }
    sh[threadIdx.x] = v;
    __syncthreads();
    for (int off = 1; off < 1024; off <<= 1) {
        int tv = (threadIdx.x >= off) ? sh[threadIdx.x - off] : 0;
        __syncthreads();
        sh[threadIdx.x] += tv;
        __syncthreads();
    }
    if (i < NV) g_rowptr[i] = sh[threadIdx.x] - v;
    if (threadIdx.x == 1023) g_bsum[blockIdx.x] = sh[1023];
}

__global__ void k_scan2(int nb) {
    if (threadIdx.x == 0) {
        int s = 0;
        for (int i = 0; i < nb; i++) { int v = g_bsum[i]; g_bsum[i] = s; s += v; }
    }
}

__global__ void k_scan3() {
    int i = blockIdx.x * blockDim.x + threadIdx.x;
    if (i < NV) {
        int r = g_rowptr[i] + g_bsum[i >> 10];
        g_rowptr[i] = r;
        g_cursor[i] = r;
    }
    if (i == 0) g_rowptr[NV] = ET;
}

__global__ void k_fill_edges(const int* __restrict__ ei) {
    int stride = gridDim.x * blockDim.x;
    for (int i = blockIdx.x * blockDim.x + threadIdx.x; i < EV; i += stride) {
        int s = ei[i], d = ei[EV + i];
        int pos = atomicAdd(&g_cursor[d], 1);
        g_edge[pos] = make_int2(s, pack_w_h2(g_dinv[s] * g_dinv[d]));
    }
}

__global__ void k_fill_self() {
    int i = blockIdx.x * blockDim.x + threadIdx.x;
    if (i < NV) {
        int pos = atomicAdd(&g_cursor[i], 1);
        float di = g_dinv[i];
        g_edge[pos] = make_int2(i, pack_w_h2(di * di));
    }
}

// ---------------- diffusion ----------------
__global__ void k_init_h0(const float* __restrict__ x) {
    int i = blockIdx.x * blockDim.x + threadIdx.x;
    if (i >= NV * 32) return;
    float4 xv = reinterpret_cast<const float4*>(x)[i];
    g_h[0][i] = pack_fp8x4(xv.x, xv.y, xv.z, xv.w);
}

// 4 edges per LDG.128 -- plain dynamic loop (compiler pipelines), unroll 4 (LOCKED)
__global__ __launch_bounds__(256) void k_hop(const unsigned int* __restrict__ hin,
                                             unsigned int* __restrict__ hout) {
    int w = (blockIdx.x * blockDim.x + threadIdx.x) >> 5;
    int lane = threadIdx.x & 31;
    if (w >= NV) return;
    int g = lane >> 3;
    int p = lane & 7;

    int beg = g_rowptr[w], end = g_rowptr[w + 1];
    __half2 acc[8];
    #pragma unroll
    for (int i = 0; i < 8; i++) acc[i] = __float2half2_rn(0.f);

    for (int base = beg; base < end; base += 32) {
        int cnt = min(32, end - base);
        int2 e = (lane < cnt) ? g_edge[base + lane] : make_int2(0, 0);  // pad: s=0, w=0
        int steps = (cnt + 3) >> 2;
        #pragma unroll 4
        for (int st = 0; st < steps; st++) {
            int jj = st * 4 + g;
            int s  = __shfl_sync(FULLMASK, e.x, jj);
            int wb = __shfl_sync(FULLMASK, e.y, jj);
            __half2 hw = *reinterpret_cast<__half2*>(&wb);   // pre-splatted half2(w,w)
            uint4 u = __ldg(reinterpret_cast<const uint4*>(hin + s * 32) + p);
            acc[0] = __hfma2(hw, fp8lo_h2(u.x), acc[0]);
            acc[1] = __hfma2(hw, fp8hi_h2(u.x), acc[1]);
            acc[2] = __hfma2(hw, fp8lo_h2(u.y), acc[2]);
            acc[3] = __hfma2(hw, fp8hi_h2(u.y), acc[3]);
            acc[4] = __hfma2(hw, fp8lo_h2(u.z), acc[4]);
            acc[5] = __hfma2(hw, fp8hi_h2(u.z), acc[5]);
            acc[6] = __hfma2(hw, fp8lo_h2(u.w), acc[6]);
            acc[7] = __hfma2(hw, fp8hi_h2(u.w), acc[7]);
        }
    }
    #pragma unroll
    for (int i = 0; i < 8; i++) {
        unsigned int v = *reinterpret_cast<unsigned int*>(&acc[i]);
        unsigned int o = __shfl_xor_sync(FULLMASK, v, 8);
        __half2 tt = __hadd2(acc[i], *reinterpret_cast<__half2*>(&o));
        unsigned int v2 = *reinterpret_cast<unsigned int*>(&tt);
        unsigned int o2 = __shfl_xor_sync(FULLMASK, v2, 16);
        acc[i] = __hadd2(tt, *reinterpret_cast<__half2*>(&o2));
    }
    if (g == 0) {
        unsigned int r[4];
        #pragma unroll
        for (int i = 0; i < 4; i++) {
            __half2_raw a = *reinterpret_cast<__half2_raw*>(&acc[2 * i]);
            __half2_raw b = *reinterpret_cast<__half2_raw*>(&acc[2 * i + 1]);
            unsigned int lo = __nv_cvt_halfraw2_to_fp8x2(a, __NV_SATFINITE, __NV_E4M3);
            unsigned int hi = __nv_cvt_halfraw2_to_fp8x2(b, __NV_SATFINITE, __NV_E4M3);
            r[i] = lo | (hi << 16);
        }
        reinterpret_cast<uint4*>(hout + w * 32)[p] = make_uint4(r[0], r[1], r[2], r[3]);
    }
}

// -------- GEMM1 [N,128]@[128,64] + Taylor combine + attention logits --------
__global__ __launch_bounds__(256) void k_gemm1(const float* __restrict__ t,
                                               const float* __restrict__ W1,
                                               const float* __restrict__ as1,
                                               const float* __restrict__ ad1) {
    __shared__ __align__(16) float sW[64 * 64];
    __shared__ float sX[32][132];
    int tid = threadIdx.x;
    int nb = blockIdx.x * 32;

    for (int i = tid; i < 1024; i += 256) {
        int r = i >> 5, q = i & 31;
        int n = nb + r;
        float4 a = make_float4(0, 0, 0, 0);
        if (n < NV) {
            float4 tv = reinterpret_cast<const float4*>(t)[q];
            float4 cf;
            cf.x = __expf(-tv.x); cf.y = __expf(-tv.y);
            cf.z = __expf(-tv.z); cf.w = __expf(-tv.w);
            #pragma unroll
            for (int k = 0; k <= 10; k++) {
                if (k > 0) {
                    float inv = 1.f / (float)k;
                    cf.x *= tv.x * inv; cf.y *= tv.y * inv;
                    cf.z *= tv.z * inv; cf.w *= tv.w * inv;
                }
                unsigned int u = __ldg(&g_h[k][n * 32 + q]);
                float2 lo, hi;
                unpack_fp8x4(u, lo, hi);
                a.x = fmaf(cf.x, lo.x, a.x); a.y = fmaf(cf.y, lo.y, a.y);
                a.z = fmaf(cf.z, hi.x, a.z); a.w = fmaf(cf.w, hi.y, a.w);
            }
        }
        *reinterpret_cast<float4*>(&sX[r][q * 4]) = a;
    }

    int node = tid >> 3, cs = tid & 7;
    unsigned long long acc2[4] = {0, 0, 0, 0};
    for (int ph = 0; ph < 2; ph++) {
        __syncthreads();
        const float4* W4 = reinterpret_cast<const float4*>(W1) + ph * 1024;
        for (int i = tid; i < 1024; i += 256) reinterpret_cast<float4*>(sW)[i] = W4[i];
        __syncthreads();
        const ulonglong2* sW2 = reinterpret_cast<const ulonglong2*>(sW);
        #pragma unroll 8
        for (int kk = 0; kk < 64; kk++) {
            float xv = sX[node][ph * 64 + kk];
            unsigned long long xv2;
            asm("mov.b64 %0, {%1, %1};" : "=l"(xv2) : "r"(__float_as_uint(xv)));
            ulonglong2 wa = sW2[kk * 16 + cs * 2];
            ulonglong2 wb = sW2[kk * 16 + cs * 2 + 1];
            fma_f32x2(acc2[0], xv2, wa.x);
            fma_f32x2(acc2[1], xv2, wa.y);
            fma_f32x2(acc2[2], xv2, wb.x);
            fma_f32x2(acc2[3], xv2, wb.y);
        }
    }
    float av[8];
    #pragma unroll
    for (int i = 0; i < 4; i++) {
        unsigned int lo, hi;
        asm("mov.b64 {%0, %1}, %2;" : "=r"(lo), "=r"(hi) : "l"(acc2[i]));
        av[2 * i]     = __uint_as_float(lo);
        av[2 * i + 1] = __uint_as_float(hi);
    }
    int n = nb + node;
    if (n < NV) {
        __half2* pp = &g_h1h[n * 32 + cs * 4];
        pp[0] = __floats2half2_rn(av[0], av[1]);
        pp[1] = __floats2half2_rn(av[2], av[3]);
        pp[2] = __floats2half2_rn(av[4], av[5]);
        pp[3] = __floats2half2_rn(av[6], av[7]);
        const float* s8 = as1 + cs * 8;
        const float* d8 = ad1 + cs * 8;
        float ls = 0.f, ld_ = 0.f;
        #pragma unroll
        for (int i = 0; i < 8; i++) { ls += av[i] * s8[i]; ld_ += av[i] * d8[i]; }
        g_als1[n * 8 + cs] = ls;
        g_ald1[n * 8 + cs] = ld_;
    }
}

// ---- GAT1: 4 edges/LDG.128 (lane p = head p), plain dynamic loop; no-shift softmax ----
__global__ __launch_bounds__(256) void k_gat1(const float* __restrict__ b1) {
    int w = (blockIdx.x * blockDim.x + threadIdx.x) >> 5;
    int lane = threadIdx.x & 31;
    if (w >= NV) return;
    int g = lane >> 3;
    int p = lane & 7;
    float adn = g_ald1[w * 8 + p];
    int beg = g_rowptr[w], end = g_rowptr[w + 1];

    float den = 0.f;
    float acc[8] = {0, 0, 0, 0, 0, 0, 0, 0};

    for (int base = beg; base < end; base += 32) {
        int cnt = min(32, end - base);
        int sv = (lane < cnt) ? g_edge[base + lane].x : 0;
        int steps = (cnt + 3) >> 2;
        #pragma unroll 2
        for (int st = 0; st < steps; st++) {
            int jj = st * 4 + g;
            int s = __shfl_sync(FULLMASK, sv, jj);
            uint4 u = __ldg(reinterpret_cast<const uint4*>(g_h1h + (size_t)s * 32) + p);
            float al = __ldg(&g_als1[s * 8 + p]);
            float e = al + adn;
            e = (e > 0.f) ? e : 0.2f * e;
            float ex = (jj < cnt) ? __expf(e) : 0.f;
            den += ex;
            float2 f0 = h2f2(u.x);
            float2 f1 = h2f2(u.y);
            float2 f2 = h2f2(u.z);
            float2 f3 = h2f2(u.w);
            acc[0] = fmaf(ex, f0.x, acc[0]); acc[1] = fmaf(ex, f0.y, acc[1]);
            acc[2] = fmaf(ex, f1.x, acc[2]); acc[3] = fmaf(ex, f1.y, acc[3]);
            acc[4] = fmaf(ex, f2.x, acc[4]); acc[5] = fmaf(ex, f2.y, acc[5]);
            acc[6] = fmaf(ex, f3.x, acc[6]); acc[7] = fmaf(ex, f3.y, acc[7]);
        }
    }
    den += __shfl_xor_sync(FULLMASK, den, 8);
    den += __shfl_xor_sync(FULLMASK, den, 16);
    #pragma unroll
    for (int i = 0; i < 8; i++) {
        acc[i] += __shfl_xor_sync(FULLMASK, acc[i], 8);
        acc[i] += __shfl_xor_sync(FULLMASK, acc[i], 16);
    }
    if (g == 0) {
        float inv = 1.f / fmaxf(den, 1e-16f);
        float v[8];
        #pragma unroll
        for (int i = 0; i < 8; i++) {
            float x = acc[i] * inv + b1[p * 8 + i];
            v[i] = (x > 0.f) ? x : expm1f(x);
        }
        unsigned int r[4];
        #pragma unroll
        for (int i = 0; i < 4; i++) {
            __half2 hh = __floats2half2_rn(v[2 * i], v[2 * i + 1]);
            r[i] = *reinterpret_cast<unsigned int*>(&hh);
        }
        reinterpret_cast<uint4*>(g_act1h + (size_t)w * 32)[p] = make_uint4(r[0], r[1], r[2], r[3]);
    }
}

// ---------------- GEMM2 [N,64]@[64,40] + logits (h2 padded to 64 ch) ----------------
__global__ __launch_bounds__(256) void k_gemm2(const float* __restrict__ W2,
                                               const float* __restrict__ as2,
                                               const float* __restrict__ ad2) {
    __shared__ float sW[64 * 40];
    __shared__ float sX[32][68];
    int tid = threadIdx.x;
    int nb = blockIdx.x * 32;
    for (int i = tid; i < 2560; i += 256) sW[i] = W2[i];
    for (int i = tid; i < 512; i += 256) {
        int r = i >> 4, q = i & 15;
        int n = nb + r;
        float4 v = make_float4(0, 0, 0, 0);
        if (n < NV) {
            __half2 h0 = g_act1h[n * 32 + q * 2];
            __half2 h1 = g_act1h[n * 32 + q * 2 + 1];
            float2 f0 = __half22float2(h0);
            float2 f1 = __half22float2(h1);
            v = make_float4(f0.x, f0.y, f1.x, f1.y);
        }
        *reinterpret_cast<float4*>(&sX[r][q * 4]) = v;
    }
    __syncthreads();
    int node = tid >> 3, cs = tid & 7;
    float a[5] = {0, 0, 0, 0, 0};
    #pragma unroll 4
    for (int kk = 0; kk < 64; kk++) {
        float xv = sX[node][kk];
        #pragma unroll
        for (int i = 0; i < 5; i++) a[i] = fmaf(xv, sW[kk * 40 + cs * 5 + i], a[i]);
    }
    int n = nb + node;
    float ps = 0.f, pd = 0.f;
    #pragma unroll
    for (int i = 0; i < 5; i++) { ps += a[i] * as2[cs * 5 + i]; pd += a[i] * ad2[cs * 5 + i]; }
    ps += __shfl_xor_sync(FULLMASK, ps, 1);
    ps += __shfl_xor_sync(FULLMASK, ps, 2);
    ps += __shfl_xor_sync(FULLMASK, ps, 4);
    pd += __shfl_xor_sync(FULLMASK, pd, 1);
    pd += __shfl_xor_sync(FULLMASK, pd, 2);
    pd += __shfl_xor_sync(FULLMASK, pd, 4);
    if (n < NV) {
        #pragma unroll
        for (int i = 0; i < 5; i++) g_h2h[n * 64 + cs * 5 + i] = __float2half(a[i]);
        if (cs == 0) { g_als2[n] = ps; g_ald2[n] = pd; }
    }
}

// ---- GAT2: 4 edges/LDG.128 (64-ch padded rows), plain loop + log_softmax -> out ----
__global__ __launch_bounds__(256) void k_gat2(const float* __restrict__ b2,
                                              float* __restrict__ out) {
    int w = (blockIdx.x * blockDim.x + threadIdx.x) >> 5;
    int lane = threadIdx.x & 31;
    if (w >= NV) return;
    int g = lane >> 3;
    int p = lane & 7;
    float adn = g_ald2[w];
    int beg = g_rowptr[w], end = g_rowptr[w + 1];

    float den = 0.f;
    float acc[8] = {0, 0, 0, 0, 0, 0, 0, 0};

    for (int base = beg; base < end; base += 32) {
        int cnt = min(32, end - base);
        int sv = (lane < cnt) ? g_edge[base + lane].x : 0;
        int steps = (cnt + 3) >> 2;
        #pragma unroll 2
        for (int st = 0; st < steps; st++) {
            int jj = st * 4 + g;
            int s = __shfl_sync(FULLMASK, sv, jj);
            uint4 u = __ldg(reinterpret_cast<const uint4*>(g_h2h + (size_t)s * 64) + p);
            float al = __ldg(&g_als2[s]);
            float e = al + adn;
            e = (e > 0.f) ? e : 0.2f * e;
            float ex = (jj < cnt) ? __expf(e) : 0.f;
            den += ex;
            float2 f0 = h2f2(u.x);
            float2 f1 = h2f2(u.y);
            float2 f2 = h2f2(u.z);
            float2 f3 = h2f2(u.w);
            acc[0] = fmaf(ex, f0.x, acc[0]); acc[1] = fmaf(ex, f0.y, acc[1]);
            acc[2] = fmaf(ex, f1.x, acc[2]); acc[3] = fmaf(ex, f1.y, acc[3]);
            acc[4] = fmaf(ex, f2.x, acc[4]); acc[5] = fmaf(ex, f2.y, acc[5]);
            acc[6] = fmaf(ex, f3.x, acc[6]); acc[7] = fmaf(ex, f3.y, acc[7]);
        }
    }
    den += __shfl_xor_sync(FULLMASK, den, 8);
    den += __shfl_xor_sync(FULLMASK, den, 16);
    #pragma unroll
    for (int i = 0; i < 8; i++) {
        acc[i] += __shfl_xor_sync(FULLMASK, acc[i], 8);
        acc[i] += __shfl_xor_sync(FULLMASK, acc[i], 16);
    }

    float inv = 1.f / fmaxf(den, 1e-16f);
    float v[8];
    float m = -FLT_MAX;
    #pragma unroll
    for (int i = 0; i < 8; i++) {
        float x = (p < 5) ? (acc[i] * inv + __ldg(&b2[min(p * 8 + i, 39)])) : -FLT_MAX;
        v[i] = x;
        m = fmaxf(m, x);
    }
    m = fmaxf(m, __shfl_xor_sync(FULLMASK, m, 1));
    m = fmaxf(m, __shfl_xor_sync(FULLMASK, m, 2));
    m = fmaxf(m, __shfl_xor_sync(FULLMASK, m, 4));
    float se = 0.f;
    #pragma unroll
    for (int i = 0; i < 8; i++) se += (p < 5) ? __expf(v[i] - m) : 0.f;
    se += __shfl_xor_sync(FULLMASK, se, 1);
    se += __shfl_xor_sync(FULLMASK, se, 2);
    se += __shfl_xor_sync(FULLMASK, se, 4);
    float lse = logf(se) + m;
    if (g == 0 && p < 5) {
        float4* dst = reinterpret_cast<float4*>(out + (size_t)w * 40 + p * 8);
        dst[0] = make_float4(v[0] - lse, v[1] - lse, v[2] - lse, v[3] - lse);
        dst[1] = make_float4(v[4] - lse, v[5] - lse, v[6] - lse, v[7] - lse);
    }
}

// ---------------- launch ----------------
extern "C" void kernel_launch(void* const* d_in, const int* in_sizes, int n_in,
                              void* d_out, int out_size) {
    const float* x   = (const float*)d_in[0];
    const int*   ei  = (const int*)d_in[1];
    const float* t   = (const float*)d_in[2];
    const float* W1  = (const float*)d_in[3];
    const float* as1 = (const float*)d_in[4];
    const float* ad1 = (const float*)d_in[5];
    const float* b1  = (const float*)d_in[6];
    const float* W2  = (const float*)d_in[7];
    const float* as2 = (const float*)d_in[8];
    const float* ad2 = (const float*)d_in[9];
    const float* b2  = (const float*)d_in[10];
    float* out = (float*)d_out;

    const int NB  = (NV + 255) / 256;
    const int NWB = (NV * 32 + 255) / 256;
    const int SB  = (NV + 1023) / 1024;

    // CSR build (zero_deg via memsetAsync; finish_deg folded into scan1)
    int* degAddr;
    cudaGetSymbolAddress((void**)&degAddr, g_deg);
    cudaMemsetAsync(degAddr, 0, NV * sizeof(int));
    k_count<<<2048, 256>>>(ei);
    k_scan1<<<SB, 1024>>>();
    k_scan2<<<1, 32>>>(SB);
    k_scan3<<<NB, 256>>>();
    k_fill_edges<<<2048, 256>>>(ei);
    k_fill_self<<<NB, 256>>>();

    // diffusion hops: h_k = A_hat h_{k-1}, features in fp8 e4m3
    k_init_h0<<<NWB, 256>>>(x);
    unsigned int* hbase;
    cudaGetSymbolAddress((void**)&hbase, g_h);
    for (int k = 1; k <= 10; k++)
        k_hop<<<NWB, 256>>>(hbase + (size_t)(k - 1) * NV * 32,
                            hbase + (size_t)k * NV * 32);

    // GAT layer 1 (Taylor combine fused into staging)
    k_gemm1<<<(NV + 31) / 32, 256>>>(t, W1, as1, ad1);
    k_gat1<<<NWB, 256>>>(b1);

    // GAT layer 2 + log_softmax
    k_gemm2<<<(NV + 31) / 32, 256>>>(W2, as2, ad2);
    k_gat2<<<NWB, 256>>>(b2, out);
}